// round 2
// baseline (speedup 1.0000x reference)
#include <cuda_runtime.h>
#include <cuda_bf16.h>
#include <stdint.h>

#define LN_EPS 1e-5f

#ifndef __CUDACC__
#define __launch_bounds__(x)
#endif

namespace {
constexpr int TILE       = 512;   // columns per chunk
constexpr int ZROWS      = 48;    // channels 0..47 needed for Gram operands
constexpr int P1_NCTA    = 288;   // persistent CTAs for pass1
constexpr int GRAM_E     = 1024;  // 32x32 gram block
constexpr int UE         = 48;    // row sums u[0..47]
constexpr int PART_STRIDE = GRAM_E + UE;  // 1072
constexpr int XPITCH     = 36;    // halves per transposed-X row (pass3)
}

// ---- scratch (allocation-free: __device__ globals) ----
__device__ float g_part[P1_NCTA * PART_STRIDE];
__device__ float g_gram[GRAM_E];
__device__ float g_u[UE];
__device__ __align__(16) __nv_bfloat16 g_A[64 * 32];
__device__ float g_e[64];
__device__ float g_rs[64];

// XOR/rotate swizzle inside a 512-element row keeps bank = (4r + k/2) mod 32
// -> conflict-free for both the column-wise writes and the mma fragment reads,
// while fitting exactly in 48KB static smem (48*512*2 = 49152B).
__device__ __forceinline__ int zoff(int r, int k) {
    return r * TILE + ((k + r * 8) & (TILE - 1));
}

__device__ __forceinline__ void mma_m16n8k16(
    float& d0, float& d1, float& d2, float& d3,
    uint32_t a0, uint32_t a1, uint32_t a2, uint32_t a3,
    uint32_t b0, uint32_t b1)
{
    asm volatile(
        "mma.sync.aligned.m16n8k16.row.col.f32.bf16.bf16.f32 "
        "{%0,%1,%2,%3}, {%4,%5,%6,%7}, {%8,%9}, {%0,%1,%2,%3};\n"
        : "+f"(d0), "+f"(d1), "+f"(d2), "+f"(d3)
        : "r"(a0), "r"(a1), "r"(a2), "r"(a3), "r"(b0), "r"(b1));
}

__device__ __forceinline__ uint32_t lds_u32(const __nv_bfloat16* p) {
    return *reinterpret_cast<const uint32_t*>(p);
}

// ============================================================================
// Pass 1: stats + bf16 Z + 32x32 Gram partials (rows [0,32) x [16,48)) + u[48]
// ============================================================================
__global__ __launch_bounds__(256) void k_pass1(const float* __restrict__ x,
                                               int N, int nchunks)
{
    __shared__ __nv_bfloat16 Zs[ZROWS * TILE];

    const int tid  = threadIdx.x;
    const int warp = tid >> 5;
    const int lane = tid & 31;
    const int g4   = lane >> 2;   // groupID 0..7
    const int t4   = lane & 3;    // threadID in group

    const int m_off = (warp >> 2) << 4;  // 0 / 16
    const int n_off = (warp & 3) << 3;   // 0,8,16,24

    float d0 = 0.f, d1 = 0.f, d2 = 0.f, d3 = 0.f;
    float ured[6];
#pragma unroll
    for (int i = 0; i < 6; i++) ured[i] = 0.f;

    for (int chunk = blockIdx.x; chunk < nchunks; chunk += gridDim.x) {
        const long col0 = (long)chunk * TILE;

        // ---- phase A: per-column stats, store z = (x-mu)*rstd as bf16 ----
#pragma unroll 1
        for (int cc = 0; cc < 2; cc++) {
            const int lc = tid + cc * 256;
            const long col = col0 + lc;
            if (col < N) {
                const float* xp = x + col;
                float s1 = 0.f, s2 = 0.f;
#pragma unroll
                for (int r = 0; r < 64; r++) {
                    float v = __ldg(xp + (size_t)r * N);
                    s1 += v;
                    s2 += v * v;
                    if (r < ZROWS) Zs[zoff(r, lc)] = __float2bfloat16(v);
                }
                const float mu   = s1 * (1.f / 64.f);
                const float var  = s2 * (1.f / 64.f) - mu * mu;
                const float rinv = rsqrtf(var + LN_EPS);
#pragma unroll
                for (int r = 0; r < ZROWS; r++) {
                    float v = __bfloat162float(Zs[zoff(r, lc)]);
                    Zs[zoff(r, lc)] = __float2bfloat16((v - mu) * rinv);
                }
            } else {
#pragma unroll
                for (int r = 0; r < ZROWS; r++)
                    Zs[zoff(r, lc)] = __float2bfloat16(0.f);
            }
        }
        __syncthreads();

        // ---- row sums u (warp w owns rows w, w+8, ..., w+40) ----
#pragma unroll
        for (int rr = 0; rr < 6; rr++) {
            const int row = warp + rr * 8;
            float s = 0.f;
#pragma unroll
            for (int c = lane; c < TILE; c += 32)
                s += __bfloat162float(Zs[zoff(row, c)]);
#pragma unroll
            for (int off = 16; off; off >>= 1)
                s += __shfl_xor_sync(0xffffffffu, s, off);
            ured[rr] += s;
        }

        // ---- Gram mma: D[32x32] += Z[0:32] * Z[16:48]^T over 512 columns ----
#pragma unroll 4
        for (int kk = 0; kk < TILE / 16; kk++) {
            const int k0 = kk * 16 + t4 * 2;
            const int ra = m_off + g4;
            const int rb = 16 + n_off + g4;
            uint32_t a0 = lds_u32(&Zs[zoff(ra,     k0)]);
            uint32_t a1 = lds_u32(&Zs[zoff(ra + 8, k0)]);
            uint32_t a2 = lds_u32(&Zs[zoff(ra,     k0 + 8)]);
            uint32_t a3 = lds_u32(&Zs[zoff(ra + 8, k0 + 8)]);
            uint32_t b0 = lds_u32(&Zs[zoff(rb,     k0)]);
            uint32_t b1 = lds_u32(&Zs[zoff(rb,     k0 + 8)]);
            mma_m16n8k16(d0, d1, d2, d3, a0, a1, a2, a3, b0, b1);
        }
        __syncthreads();
    }

    // ---- write deterministic per-CTA partials ----
    float* pp = g_part + (size_t)blockIdx.x * PART_STRIDE;
    const int row0 = m_off + g4;
    const int colp = n_off + t4 * 2;
    pp[row0 * 32 + colp]           = d0;
    pp[row0 * 32 + colp + 1]       = d1;
    pp[(row0 + 8) * 32 + colp]     = d2;
    pp[(row0 + 8) * 32 + colp + 1] = d3;
    if (lane == 0) {
#pragma unroll
        for (int rr = 0; rr < 6; rr++)
            pp[GRAM_E + warp + rr * 8] = ured[rr];
    }
}

// ============================================================================
// Reduce partials (deterministic tree-free sum; 1072 entries x nb CTAs)
// ============================================================================
__global__ void k_reduce(int nb)
{
    const int e = blockIdx.x * blockDim.x + threadIdx.x;
    if (e >= PART_STRIDE) return;
    float s = 0.f;
    for (int c = 0; c < nb; c++) s += g_part[(size_t)c * PART_STRIDE + e];
    if (e < GRAM_E) g_gram[e] = s;
    else            g_u[e - GRAM_E] = s;
}

// ============================================================================
// Pass 2 (1 block, 64 threads): logits -> softmax -> A[64x32], e[64], rs[64]
// ============================================================================
__global__ void k_pass2(const float* __restrict__ gamma,
                        const float* __restrict__ beta,
                        const float* __restrict__ cw,
                        const float* __restrict__ cb,
                        float Nf)
{
    __shared__ float Gs[GRAM_E];
    __shared__ float us[UE];
    __shared__ float gs[64], bs[64];

    const int c = threadIdx.x;  // output row 0..63
    for (int i = c; i < GRAM_E; i += 64) Gs[i] = g_gram[i];
    if (c < UE) us[c] = g_u[c];
    gs[c] = gamma[c];
    bs[c] = beta[c];
    __syncthreads();

    const float wq = cw[c], bq = cb[c];
    const int   iq = c / 3;
    const float gi = gs[iq], bi = bs[iq], ui = us[iq];
    const float ti = gi * ui + Nf * bi;

    float L[64];
    float mx = -1e30f;
#pragma unroll 1
    for (int b2 = 0; b2 < 64; b2++) {
        const int   ik = (64 + b2) / 3;        // 21..42
        const float wk = cw[64 + b2], bk = cb[64 + b2];
        const float gj = gs[ik], bj = bs[ik], uj = us[ik];
        const float tj = gj * uj + Nf * bj;
        const float Gz = Gs[iq * 32 + (ik - 16)];
        const float S  = gi * gj * Gz + gi * bj * ui + bi * gj * uj + Nf * bi * bj;
        const float l  = 0.125f * (wq * wk * S + wq * bk * ti + bq * wk * tj + Nf * bq * bk);
        L[b2] = l;
        mx = fmaxf(mx, l);
    }
    float se = 0.f;
#pragma unroll 1
    for (int b2 = 0; b2 < 64; b2++) {
        const float ev = expf(L[b2] - mx);
        L[b2] = ev;
        se += ev;
    }
    const float inv = 1.f / se;

    float eacc = 0.f;
#pragma unroll 1
    for (int b2 = 0; b2 < 64; b2++) {
        L[b2] *= inv;                       // attn[c][b2]
        eacc += L[b2] * cb[128 + b2];       // attn . conv_b(v)
    }

    float rssum = 0.f;
#pragma unroll 1
    for (int j = 32; j < 64; j++) {
        float P = 0.f;
        const int b0 = 3 * j - 128;         // v-channel b with (128+b)/3 == j
#pragma unroll
        for (int d = 0; d < 3; d++) {
            const int bb = b0 + d;
            if (bb >= 0 && bb < 64) P += L[bb] * cw[128 + bb];
        }
        const float Av = P * gs[j];
        const __nv_bfloat16 ab = __float2bfloat16(Av);
        g_A[c * 32 + (j - 32)] = ab;
        rssum += __bfloat162float(ab);      // rs from bf16-rounded A for consistency
        eacc  += P * bs[j];
    }
    g_e[c]  = eacc;
    g_rs[c] = rssum;
}

// ============================================================================
// Pass 3: out = x + r*(A@x - mu*rs) + e, fused GEMM + epilogue
// ============================================================================
__global__ __launch_bounds__(256) void k_pass3(const float* __restrict__ x,
                                               float* __restrict__ out, int N)
{
    __shared__ __nv_bfloat16 XsT[TILE * XPITCH];  // transposed rows 32..63, bf16
    __shared__ float mus[TILE], rvs[TILE];

    const int tid  = threadIdx.x;
    const int warp = tid >> 5;
    const int lane = tid & 31;
    const int g4   = lane >> 2;
    const int t4   = lane & 3;

    const long col0 = (long)blockIdx.x * TILE;

    // ---- phase A: stats + bf16 x rows 32..63 transposed into smem ----
#pragma unroll 1
    for (int cc = 0; cc < 2; cc++) {
        const int lc = tid + cc * 256;
        const long col = col0 + lc;
        float s1 = 0.f, s2 = 0.f;
        if (col < N) {
            const float* xp = x + col;
#pragma unroll
            for (int r = 0; r < 64; r++) {
                float v = __ldg(xp + (size_t)r * N);
                s1 += v;
                s2 += v * v;
                if (r >= 32) XsT[lc * XPITCH + (r - 32)] = __float2bfloat16(v);
            }
        } else {
#pragma unroll
            for (int r = 0; r < 32; r++)
                XsT[lc * XPITCH + r] = __float2bfloat16(0.f);
        }
        const float mu  = s1 * (1.f / 64.f);
        const float var = s2 * (1.f / 64.f) - mu * mu;
        mus[lc] = mu;
        rvs[lc] = rsqrtf(var + LN_EPS);
    }
    __syncthreads();

    // ---- phase B: mma over m=64 (4 tiles) x k=32 x n=512; warp -> (m,n-half)
    const int m_off  = (warp & 3) << 4;
    const int n_half = warp >> 2;
    const int row0   = m_off + g4;
    const int row1   = row0 + 8;

    // preload A fragments (fixed for all n)
    uint32_t Af[2][4];
#pragma unroll
    for (int s = 0; s < 2; s++) {
        const int k0 = s * 16 + t4 * 2;
        Af[s][0] = *reinterpret_cast<const uint32_t*>(&g_A[row0 * 32 + k0]);
        Af[s][1] = *reinterpret_cast<const uint32_t*>(&g_A[row1 * 32 + k0]);
        Af[s][2] = *reinterpret_cast<const uint32_t*>(&g_A[row0 * 32 + k0 + 8]);
        Af[s][3] = *reinterpret_cast<const uint32_t*>(&g_A[row1 * 32 + k0 + 8]);
    }
    const float e0  = g_e[row0],  e1  = g_e[row1];
    const float rs0 = g_rs[row0], rs1 = g_rs[row1];

#pragma unroll 2
    for (int nc = 0; nc < 32; nc++) {
        const int nb   = n_half * 256 + nc * 8;
        const int nrow = nb + g4;
        const __nv_bfloat16* bp = &XsT[nrow * XPITCH];
        uint32_t b00 = lds_u32(bp + t4 * 2);
        uint32_t b01 = lds_u32(bp + t4 * 2 + 8);
        uint32_t b10 = lds_u32(bp + t4 * 2 + 16);
        uint32_t b11 = lds_u32(bp + t4 * 2 + 24);

        float c0 = 0.f, c1 = 0.f, c2 = 0.f, c3 = 0.f;
        mma_m16n8k16(c0, c1, c2, c3, Af[0][0], Af[0][1], Af[0][2], Af[0][3], b00, b01);
        mma_m16n8k16(c0, c1, c2, c3, Af[1][0], Af[1][1], Af[1][2], Af[1][3], b10, b11);

        // ---- fused epilogue ----
        const int  lcol = nb + t4 * 2;
        const long gc   = col0 + lcol;
        if (gc + 1 < N) {
            const float mu0 = mus[lcol],     mu1 = mus[lcol + 1];
            const float rv0 = rvs[lcol],     rv1 = rvs[lcol + 1];

            const float2 xv0 = *reinterpret_cast<const float2*>(x + (size_t)row0 * N + gc);
            float2 o0;
            o0.x = xv0.x + e0 + rv0 * (c0 - mu0 * rs0);
            o0.y = xv0.y + e0 + rv1 * (c1 - mu1 * rs0);
            *reinterpret_cast<float2*>(out + (size_t)row0 * N + gc) = o0;

            const float2 xv1 = *reinterpret_cast<const float2*>(x + (size_t)row1 * N + gc);
            float2 o1;
            o1.x = xv1.x + e1 + rv0 * (c2 - mu0 * rs1);
            o1.y = xv1.y + e1 + rv1 * (c3 - mu1 * rs1);
            *reinterpret_cast<float2*>(out + (size_t)row1 * N + gc) = o1;
        } else if (gc < N) {
            const float mu0 = mus[lcol], rv0 = rvs[lcol];
            const float xa = x[(size_t)row0 * N + gc];
            out[(size_t)row0 * N + gc] = xa + e0 + rv0 * (c0 - mu0 * rs0);
            const float xb = x[(size_t)row1 * N + gc];
            out[(size_t)row1 * N + gc] = xb + e1 + rv0 * (c2 - mu0 * rs1);
        }
    }
}

// ============================================================================
extern "C" void kernel_launch(void* const* d_in, const int* in_sizes, int n_in,
                              void* d_out, int out_size)
{
    const float* x     = (const float*)d_in[0];
    const float* gamma = (const float*)d_in[1];
    const float* beta  = (const float*)d_in[2];
    const float* cw    = (const float*)d_in[3];
    const float* cb    = (const float*)d_in[4];
    float* out = (float*)d_out;

    const int N = in_sizes[0] / 64;
    const int nchunks = (N + TILE - 1) / TILE;
    const int nb1 = nchunks < P1_NCTA ? nchunks : P1_NCTA;

    k_pass1<<<nb1, 256>>>(x, N, nchunks);
    k_reduce<<<(PART_STRIDE + 255) / 256, 256>>>(nb1);
    k_pass2<<<1, 64>>>(gamma, beta, cw, cb, (float)N);
    k_pass3<<<nchunks, 256>>>(x, out, N);
}

// round 3
// speedup vs baseline: 1.0261x; 1.0261x over previous
#include <cuda_runtime.h>
#include <cuda_bf16.h>
#include <stdint.h>

#define LN_EPS 1e-5f

namespace {
constexpr int TILE       = 512;   // columns per chunk
constexpr int ZROWS      = 48;    // channels 0..47 needed for Gram operands
constexpr int P1_NCTA    = 288;   // persistent CTAs for pass1
constexpr int GRAM_E     = 1024;  // 32x32 gram block
constexpr int UE         = 48;    // row sums u[0..47]
constexpr int PART_STRIDE = GRAM_E + UE;  // 1072
constexpr int XPITCH_W   = 17;    // words per transposed-X col (pass3): 34 halves, odd word pitch
}

// ---- scratch (allocation-free: __device__ globals) ----
__device__ float g_part[P1_NCTA * PART_STRIDE];
__device__ float g_gram[GRAM_E];
__device__ float g_u[UE];
__device__ __align__(16) __nv_bfloat16 g_A[64 * 32];
__device__ float g_e[64];
__device__ float g_rs[64];

// Zs logical layout: [row][col], swizzled: half-index = r*512 + ((k + r*8) & 511)
__device__ __forceinline__ int zoff(int r, int k) {
    return r * TILE + ((k + r * 8) & (TILE - 1));
}

__device__ __forceinline__ void mma_m16n8k16(
    float& d0, float& d1, float& d2, float& d3,
    uint32_t a0, uint32_t a1, uint32_t a2, uint32_t a3,
    uint32_t b0, uint32_t b1)
{
    asm volatile(
        "mma.sync.aligned.m16n8k16.row.col.f32.bf16.bf16.f32 "
        "{%0,%1,%2,%3}, {%4,%5,%6,%7}, {%8,%9}, {%0,%1,%2,%3};\n"
        : "+f"(d0), "+f"(d1), "+f"(d2), "+f"(d3)
        : "r"(a0), "r"(a1), "r"(a2), "r"(a3), "r"(b0), "r"(b1));
}

__device__ __forceinline__ uint32_t lds_u32(const __nv_bfloat16* p) {
    return *reinterpret_cast<const uint32_t*>(p);
}

__device__ __forceinline__ uint32_t pack_bf16(float lo, float hi) {
    __nv_bfloat162 b = __floats2bfloat162_rn(lo, hi);
    return *reinterpret_cast<uint32_t*>(&b);
}

// ============================================================================
// Pass 1: stats + bf16 Z + 32x32 Gram partials (rows [0,32) x [16,48)) + u[48]
// ============================================================================
__global__ __launch_bounds__(256) void k_pass1(const float* __restrict__ x,
                                               int N, int nchunks)
{
    __shared__ uint32_t Zs32[ZROWS * TILE / 2];   // 48KB exactly
    __nv_bfloat16* zh = reinterpret_cast<__nv_bfloat16*>(Zs32);

    const int tid  = threadIdx.x;
    const int warp = tid >> 5;
    const int lane = tid & 31;
    const int g4   = lane >> 2;
    const int t4   = lane & 3;

    const int m_off = (warp >> 2) << 4;  // 0 / 16
    const int n_off = (warp & 3) << 3;   // 0,8,16,24

    float d0 = 0.f, d1 = 0.f, d2 = 0.f, d3 = 0.f;
    float ured[6];
#pragma unroll
    for (int i = 0; i < 6; i++) ured[i] = 0.f;

    for (int chunk = blockIdx.x; chunk < nchunks; chunk += gridDim.x) {
        const long col0 = (long)chunk * TILE;
        const bool fast = (col0 + TILE <= (long)N) && ((N & 1) == 0);

        if (fast) {
            // ---- phase A fast: each thread owns 2 adjacent cols, float2 loads
            const float* xp = x + col0 + 2 * tid;
            float s1x = 0.f, s1y = 0.f, s2x = 0.f, s2y = 0.f;
#pragma unroll
            for (int r = 0; r < 64; r++) {
                float2 v = __ldg(reinterpret_cast<const float2*>(xp + (size_t)r * N));
                s1x += v.x; s1y += v.y;
                s2x = fmaf(v.x, v.x, s2x);
                s2y = fmaf(v.y, v.y, s2y);
                if (r < ZROWS)
                    Zs32[r * 256 + ((tid + r * 4) & 255)] = pack_bf16(v.x, v.y);
            }
            const float mux = s1x * (1.f / 64.f), muy = s1y * (1.f / 64.f);
            const float rix = rsqrtf(s2x * (1.f / 64.f) - mux * mux + LN_EPS);
            const float riy = rsqrtf(s2y * (1.f / 64.f) - muy * muy + LN_EPS);
            // renormalize own columns (no sync needed: single-owner)
#pragma unroll
            for (int r = 0; r < ZROWS; r++) {
                const int w = r * 256 + ((tid + r * 4) & 255);
                uint32_t u = Zs32[w];
                __nv_bfloat162 b = *reinterpret_cast<__nv_bfloat162*>(&u);
                float zx = (__bfloat162float(b.x) - mux) * rix;
                float zy = (__bfloat162float(b.y) - muy) * riy;
                Zs32[w] = pack_bf16(zx, zy);
            }
        } else {
            // ---- slow scalar fallback (tail chunk / odd N) ----
#pragma unroll 1
            for (int cc = 0; cc < 2; cc++) {
                const int lc = 2 * tid + cc;
                const long col = col0 + lc;
                if (col < N) {
                    const float* xp = x + col;
                    float s1 = 0.f, s2 = 0.f;
#pragma unroll 1
                    for (int r = 0; r < 64; r++) {
                        float v = __ldg(xp + (size_t)r * N);
                        s1 += v; s2 = fmaf(v, v, s2);
                        if (r < ZROWS) zh[zoff(r, lc)] = __float2bfloat16(v);
                    }
                    const float mu = s1 * (1.f / 64.f);
                    const float ri = rsqrtf(s2 * (1.f / 64.f) - mu * mu + LN_EPS);
#pragma unroll 1
                    for (int r = 0; r < ZROWS; r++) {
                        float v = __bfloat162float(zh[zoff(r, lc)]);
                        zh[zoff(r, lc)] = __float2bfloat16((v - mu) * ri);
                    }
                } else {
#pragma unroll 1
                    for (int r = 0; r < ZROWS; r++)
                        zh[zoff(r, lc)] = __float2bfloat16(0.f);
                }
            }
        }
        __syncthreads();

        // ---- row sums u via bf16x2, conflict-free (lane word-stride 1) ----
#pragma unroll
        for (int rr = 0; rr < 6; rr++) {
            const int row = warp + rr * 8;
            float s = 0.f;
#pragma unroll
            for (int i = 0; i < 8; i++) {
                const int w = row * 256 + ((lane + 32 * i + row * 4) & 255);
                uint32_t u = Zs32[w];
                __nv_bfloat162 b = *reinterpret_cast<__nv_bfloat162*>(&u);
                s += __bfloat162float(b.x) + __bfloat162float(b.y);
            }
#pragma unroll
            for (int off = 16; off; off >>= 1)
                s += __shfl_xor_sync(0xffffffffu, s, off);
            ured[rr] += s;
        }

        // ---- Gram mma: D[32x32] += Z[0:32] * Z[16:48]^T over 512 columns ----
#pragma unroll 4
        for (int kk = 0; kk < TILE / 16; kk++) {
            const int k0 = kk * 16 + t4 * 2;
            const int ra = m_off + g4;
            const int rb = 16 + n_off + g4;
            uint32_t a0 = lds_u32(&zh[zoff(ra,     k0)]);
            uint32_t a1 = lds_u32(&zh[zoff(ra + 8, k0)]);
            uint32_t a2 = lds_u32(&zh[zoff(ra,     k0 + 8)]);
            uint32_t a3 = lds_u32(&zh[zoff(ra + 8, k0 + 8)]);
            uint32_t b0 = lds_u32(&zh[zoff(rb,     k0)]);
            uint32_t b1 = lds_u32(&zh[zoff(rb,     k0 + 8)]);
            mma_m16n8k16(d0, d1, d2, d3, a0, a1, a2, a3, b0, b1);
        }
        __syncthreads();
    }

    // ---- write deterministic per-CTA partials ----
    float* pp = g_part + (size_t)blockIdx.x * PART_STRIDE;
    const int row0 = m_off + g4;
    const int colp = n_off + t4 * 2;
    pp[row0 * 32 + colp]           = d0;
    pp[row0 * 32 + colp + 1]       = d1;
    pp[(row0 + 8) * 32 + colp]     = d2;
    pp[(row0 + 8) * 32 + colp + 1] = d3;
    if (lane == 0) {
#pragma unroll
        for (int rr = 0; rr < 6; rr++)
            pp[GRAM_E + warp + rr * 8] = ured[rr];
    }
}

// ============================================================================
// Reduce partials (deterministic)
// ============================================================================
__global__ void k_reduce(int nb)
{
    const int e = blockIdx.x * blockDim.x + threadIdx.x;
    if (e >= PART_STRIDE) return;
    float s = 0.f;
    for (int c = 0; c < nb; c++) s += g_part[(size_t)c * PART_STRIDE + e];
    if (e < GRAM_E) g_gram[e] = s;
    else            g_u[e - GRAM_E] = s;
}

// ============================================================================
// Pass 2 (1 block, 64 threads): logits -> softmax -> A[64x32], e[64], rs[64]
// ============================================================================
__global__ void k_pass2(const float* __restrict__ gamma,
                        const float* __restrict__ beta,
                        const float* __restrict__ cw,
                        const float* __restrict__ cb,
                        float Nf)
{
    __shared__ float Gs[GRAM_E];
    __shared__ float us[UE];
    __shared__ float gs[64], bs[64];

    const int c = threadIdx.x;
    for (int i = c; i < GRAM_E; i += 64) Gs[i] = g_gram[i];
    if (c < UE) us[c] = g_u[c];
    gs[c] = gamma[c];
    bs[c] = beta[c];
    __syncthreads();

    const float wq = cw[c], bq = cb[c];
    const int   iq = c / 3;
    const float gi = gs[iq], bi = bs[iq], ui = us[iq];
    const float ti = gi * ui + Nf * bi;

    float L[64];
    float mx = -1e30f;
#pragma unroll 1
    for (int b2 = 0; b2 < 64; b2++) {
        const int   ik = (64 + b2) / 3;
        const float wk = cw[64 + b2], bk = cb[64 + b2];
        const float gj = gs[ik], bj = bs[ik], uj = us[ik];
        const float tj = gj * uj + Nf * bj;
        const float Gz = Gs[iq * 32 + (ik - 16)];
        const float S  = gi * gj * Gz + gi * bj * ui + bi * gj * uj + Nf * bi * bj;
        const float l  = 0.125f * (wq * wk * S + wq * bk * ti + bq * wk * tj + Nf * bq * bk);
        L[b2] = l;
        mx = fmaxf(mx, l);
    }
    float se = 0.f;
#pragma unroll 1
    for (int b2 = 0; b2 < 64; b2++) {
        const float ev = expf(L[b2] - mx);
        L[b2] = ev;
        se += ev;
    }
    const float inv = 1.f / se;

    float eacc = 0.f;
#pragma unroll 1
    for (int b2 = 0; b2 < 64; b2++) {
        L[b2] *= inv;
        eacc += L[b2] * cb[128 + b2];
    }

    float rssum = 0.f;
#pragma unroll 1
    for (int j = 32; j < 64; j++) {
        float P = 0.f;
        const int b0 = 3 * j - 128;
#pragma unroll
        for (int d = 0; d < 3; d++) {
            const int bb = b0 + d;
            if (bb >= 0 && bb < 64) P += L[bb] * cw[128 + bb];
        }
        const float Av = P * gs[j];
        const __nv_bfloat16 ab = __float2bfloat16(Av);
        g_A[c * 32 + (j - 32)] = ab;
        rssum += __bfloat162float(ab);
        eacc  += P * bs[j];
    }
    g_e[c]  = eacc;
    g_rs[c] = rssum;
}

// ============================================================================
// Pass 3: out = x + r*(A@x - mu*rs) + e, fused GEMM + epilogue
// ============================================================================
__global__ __launch_bounds__(256) void k_pass3(const float* __restrict__ x,
                                               float* __restrict__ out, int N)
{
    __shared__ uint32_t XsT32[TILE * XPITCH_W];   // [col][rowpair], 34KB
    __shared__ float mus[TILE], rvs[TILE];
    __nv_bfloat16* xh = reinterpret_cast<__nv_bfloat16*>(XsT32);

    const int tid  = threadIdx.x;
    const int warp = tid >> 5;
    const int lane = tid & 31;
    const int g4   = lane >> 2;
    const int t4   = lane & 3;

    const long col0 = (long)blockIdx.x * TILE;
    const bool fast = (col0 + TILE <= (long)N) && ((N & 1) == 0);

    if (fast) {
        // ---- phase A fast: 2 adjacent cols per thread, float2 loads ----
        const int c0 = 2 * tid;
        const float* xp = x + col0 + c0;
        float s1x = 0.f, s1y = 0.f, s2x = 0.f, s2y = 0.f;
#pragma unroll
        for (int r = 0; r < 32; r++) {
            float2 v = __ldg(reinterpret_cast<const float2*>(xp + (size_t)r * N));
            s1x += v.x; s1y += v.y;
            s2x = fmaf(v.x, v.x, s2x);
            s2y = fmaf(v.y, v.y, s2y);
        }
#pragma unroll
        for (int rp = 0; rp < 16; rp++) {
            float2 va = __ldg(reinterpret_cast<const float2*>(xp + (size_t)(32 + 2 * rp) * N));
            float2 vb = __ldg(reinterpret_cast<const float2*>(xp + (size_t)(33 + 2 * rp) * N));
            s1x += va.x + vb.x; s1y += va.y + vb.y;
            s2x = fmaf(va.x, va.x, s2x); s2x = fmaf(vb.x, vb.x, s2x);
            s2y = fmaf(va.y, va.y, s2y); s2y = fmaf(vb.y, vb.y, s2y);
            XsT32[c0 * XPITCH_W + rp]       = pack_bf16(va.x, vb.x);
            XsT32[(c0 + 1) * XPITCH_W + rp] = pack_bf16(va.y, vb.y);
        }
        const float mux = s1x * (1.f / 64.f), muy = s1y * (1.f / 64.f);
        mus[c0]     = mux;
        mus[c0 + 1] = muy;
        rvs[c0]     = rsqrtf(s2x * (1.f / 64.f) - mux * mux + LN_EPS);
        rvs[c0 + 1] = rsqrtf(s2y * (1.f / 64.f) - muy * muy + LN_EPS);
    } else {
        // ---- slow scalar fallback ----
#pragma unroll 1
        for (int cc = 0; cc < 2; cc++) {
            const int lc = 2 * tid + cc;
            const long col = col0 + lc;
            float s1 = 0.f, s2 = 0.f;
            if (col < N) {
                const float* xp = x + col;
#pragma unroll 1
                for (int r = 0; r < 64; r++) {
                    float v = __ldg(xp + (size_t)r * N);
                    s1 += v; s2 = fmaf(v, v, s2);
                    if (r >= 32) xh[lc * (2 * XPITCH_W) + (r - 32)] = __float2bfloat16(v);
                }
            } else {
#pragma unroll 1
                for (int r = 0; r < 32; r++)
                    xh[lc * (2 * XPITCH_W) + r] = __float2bfloat16(0.f);
            }
            const float mu = s1 * (1.f / 64.f);
            mus[lc] = mu;
            rvs[lc] = rsqrtf(s2 * (1.f / 64.f) - mu * mu + LN_EPS);
        }
    }
    __syncthreads();

    // ---- phase B: mma over m=64 (4 tiles) x k=32 x n=512 ----
    const int m_off  = (warp & 3) << 4;
    const int n_half = warp >> 2;
    const int row0   = m_off + g4;
    const int row1   = row0 + 8;

    uint32_t Af[2][4];
#pragma unroll
    for (int s = 0; s < 2; s++) {
        const int k0 = s * 16 + t4 * 2;
        Af[s][0] = *reinterpret_cast<const uint32_t*>(&g_A[row0 * 32 + k0]);
        Af[s][1] = *reinterpret_cast<const uint32_t*>(&g_A[row1 * 32 + k0]);
        Af[s][2] = *reinterpret_cast<const uint32_t*>(&g_A[row0 * 32 + k0 + 8]);
        Af[s][3] = *reinterpret_cast<const uint32_t*>(&g_A[row1 * 32 + k0 + 8]);
    }
    const float e0  = g_e[row0],  e1  = g_e[row1];
    const float rs0 = g_rs[row0], rs1 = g_rs[row1];

#pragma unroll 4
    for (int nc = 0; nc < 32; nc++) {
        const int nb   = n_half * 256 + nc * 8;
        const int nrow = nb + g4;
        const int lcol = nb + t4 * 2;
        const long gc  = col0 + lcol;

        // issue residual loads early (L2 hits from phase A)
        float2 xv0, xv1;
        bool pair_ok = (gc + 1 < (long)N);
        if (pair_ok) {
            xv0 = __ldg(reinterpret_cast<const float2*>(x + (size_t)row0 * N + gc));
            xv1 = __ldg(reinterpret_cast<const float2*>(x + (size_t)row1 * N + gc));
        }

        const uint32_t* bp = &XsT32[nrow * XPITCH_W];
        uint32_t b00 = bp[t4];
        uint32_t b01 = bp[t4 + 4];
        uint32_t b10 = bp[t4 + 8];
        uint32_t b11 = bp[t4 + 12];

        float c0 = 0.f, c1 = 0.f, c2 = 0.f, c3 = 0.f;
        mma_m16n8k16(c0, c1, c2, c3, Af[0][0], Af[0][1], Af[0][2], Af[0][3], b00, b01);
        mma_m16n8k16(c0, c1, c2, c3, Af[1][0], Af[1][1], Af[1][2], Af[1][3], b10, b11);

        if (pair_ok) {
            const float mu0 = mus[lcol],     mu1 = mus[lcol + 1];
            const float rv0 = rvs[lcol],     rv1 = rvs[lcol + 1];
            float2 o0;
            o0.x = xv0.x + e0 + rv0 * (c0 - mu0 * rs0);
            o0.y = xv0.y + e0 + rv1 * (c1 - mu1 * rs0);
            *reinterpret_cast<float2*>(out + (size_t)row0 * N + gc) = o0;
            float2 o1;
            o1.x = xv1.x + e1 + rv0 * (c2 - mu0 * rs1);
            o1.y = xv1.y + e1 + rv1 * (c3 - mu1 * rs1);
            *reinterpret_cast<float2*>(out + (size_t)row1 * N + gc) = o1;
        } else if (gc < (long)N) {
            const float mu0 = mus[lcol], rv0 = rvs[lcol];
            const float xa = x[(size_t)row0 * N + gc];
            out[(size_t)row0 * N + gc] = xa + e0 + rv0 * (c0 - mu0 * rs0);
            const float xb = x[(size_t)row1 * N + gc];
            out[(size_t)row1 * N + gc] = xb + e1 + rv0 * (c2 - mu0 * rs1);
        }
    }
}

// ============================================================================
extern "C" void kernel_launch(void* const* d_in, const int* in_sizes, int n_in,
                              void* d_out, int out_size)
{
    const float* x     = (const float*)d_in[0];
    const float* gamma = (const float*)d_in[1];
    const float* beta  = (const float*)d_in[2];
    const float* cw    = (const float*)d_in[3];
    const float* cb    = (const float*)d_in[4];
    float* out = (float*)d_out;

    const int N = in_sizes[0] / 64;
    const int nchunks = (N + TILE - 1) / TILE;
    const int nb1 = nchunks < P1_NCTA ? nchunks : P1_NCTA;

    k_pass1<<<nb1, 256>>>(x, N, nchunks);
    k_reduce<<<(PART_STRIDE + 255) / 256, 256>>>(nb1);
    k_pass2<<<1, 64>>>(gamma, beta, cw, cb, (float)N);
    k_pass3<<<nchunks, 256>>>(x, out, N);
}

// round 4
// speedup vs baseline: 1.1246x; 1.0960x over previous
#include <cuda_runtime.h>
#include <cuda_bf16.h>
#include <stdint.h>

#define LN_EPS 1e-5f

namespace {
constexpr int TILE       = 256;    // columns per chunk
constexpr int NTHR       = 128;    // threads per CTA
constexpr int ZROWS      = 48;
constexpr int P1_NCTA    = 1184;   // 148 SMs * 8 CTAs
constexpr int GRAM_E     = 1024;
constexpr int UE         = 48;
constexpr int PART_STRIDE = GRAM_E + UE;  // 1072
constexpr int XPITCH_W   = 17;     // words per transposed-X col (pass3)
}

// ---- scratch (allocation-free: __device__ globals) ----
__device__ float g_part[P1_NCTA * PART_STRIDE];
__device__ float g_gram[GRAM_E];
__device__ float g_u[UE];
__device__ __align__(16) __nv_bfloat16 g_A[64 * 32];
__device__ float g_e[64];
__device__ float g_rs[64];

// swizzled half-index inside a 256-col row
__device__ __forceinline__ int zoff(int r, int k) {
    return r * TILE + ((k + r * 8) & (TILE - 1));
}

__device__ __forceinline__ void mma_m16n8k16(
    float& d0, float& d1, float& d2, float& d3,
    uint32_t a0, uint32_t a1, uint32_t a2, uint32_t a3,
    uint32_t b0, uint32_t b1)
{
    asm volatile(
        "mma.sync.aligned.m16n8k16.row.col.f32.bf16.bf16.f32 "
        "{%0,%1,%2,%3}, {%4,%5,%6,%7}, {%8,%9}, {%0,%1,%2,%3};\n"
        : "+f"(d0), "+f"(d1), "+f"(d2), "+f"(d3)
        : "r"(a0), "r"(a1), "r"(a2), "r"(a3), "r"(b0), "r"(b1));
}

__device__ __forceinline__ uint32_t lds_u32(const __nv_bfloat16* p) {
    return *reinterpret_cast<const uint32_t*>(p);
}

__device__ __forceinline__ uint32_t pack_bf16(float lo, float hi) {
    __nv_bfloat162 b = __floats2bfloat162_rn(lo, hi);
    return *reinterpret_cast<uint32_t*>(&b);
}

// ============================================================================
// Pass 1: stats + bf16 Z + 32x32 Gram partials (rows [0,32) x [16,48)) + u[48]
// 128 threads, TILE=256, 8 CTAs/SM
// ============================================================================
__global__ __launch_bounds__(NTHR, 8) void k_pass1(const float* __restrict__ x,
                                                   int N, int nchunks)
{
    __shared__ uint32_t Zs32[ZROWS * TILE / 2];   // 24KB
    __shared__ float us_acc[UE];
    __nv_bfloat16* zh = reinterpret_cast<__nv_bfloat16*>(Zs32);

    const int tid  = threadIdx.x;
    const int warp = tid >> 5;       // 0..3
    const int lane = tid & 31;
    const int g4   = lane >> 2;
    const int t4   = lane & 3;

    const int m_off = (warp >> 1) << 4;   // 0/16
    const int n_off = (warp & 1) << 4;    // 0/16

    float d[2][4];
#pragma unroll
    for (int j = 0; j < 2; j++)
#pragma unroll
        for (int i = 0; i < 4; i++) d[j][i] = 0.f;

    if (tid < UE) us_acc[tid] = 0.f;

    for (int chunk = blockIdx.x; chunk < nchunks; chunk += gridDim.x) {
        const long col0 = (long)chunk * TILE;
        const bool fast = (col0 + TILE <= (long)N) && ((N & 1) == 0);

        if (fast) {
            const float* xp = x + col0 + 2 * tid;
            float s1x = 0.f, s1y = 0.f, s2x = 0.f, s2y = 0.f;
#pragma unroll
            for (int r = 0; r < 64; r++) {
                float2 v = __ldcs(reinterpret_cast<const float2*>(xp + (size_t)r * N));
                s1x += v.x; s1y += v.y;
                s2x = fmaf(v.x, v.x, s2x);
                s2y = fmaf(v.y, v.y, s2y);
                if (r < ZROWS)
                    Zs32[r * 128 + ((tid + r * 4) & 127)] = pack_bf16(v.x, v.y);
            }
            const float mux = s1x * (1.f / 64.f), muy = s1y * (1.f / 64.f);
            const float rix = rsqrtf(s2x * (1.f / 64.f) - mux * mux + LN_EPS);
            const float riy = rsqrtf(s2y * (1.f / 64.f) - muy * muy + LN_EPS);
#pragma unroll
            for (int r = 0; r < ZROWS; r++) {
                const int w = r * 128 + ((tid + r * 4) & 127);
                uint32_t u = Zs32[w];
                __nv_bfloat162 b = *reinterpret_cast<__nv_bfloat162*>(&u);
                Zs32[w] = pack_bf16((__bfloat162float(b.x) - mux) * rix,
                                    (__bfloat162float(b.y) - muy) * riy);
            }
        } else {
#pragma unroll 1
            for (int cc = 0; cc < 2; cc++) {
                const int lc = 2 * tid + cc;
                const long col = col0 + lc;
                if (col < N) {
                    const float* xp = x + col;
                    float s1 = 0.f, s2 = 0.f;
#pragma unroll 1
                    for (int r = 0; r < 64; r++) {
                        float v = __ldg(xp + (size_t)r * N);
                        s1 += v; s2 = fmaf(v, v, s2);
                        if (r < ZROWS) zh[zoff(r, lc)] = __float2bfloat16(v);
                    }
                    const float mu = s1 * (1.f / 64.f);
                    const float ri = rsqrtf(s2 * (1.f / 64.f) - mu * mu + LN_EPS);
#pragma unroll 1
                    for (int r = 0; r < ZROWS; r++) {
                        float v = __bfloat162float(zh[zoff(r, lc)]);
                        zh[zoff(r, lc)] = __float2bfloat16((v - mu) * ri);
                    }
                } else {
#pragma unroll 1
                    for (int r = 0; r < ZROWS; r++)
                        zh[zoff(r, lc)] = __float2bfloat16(0.f);
                }
            }
        }
        __syncthreads();

        // ---- row sums (warp w owns rows w, w+4, ..., w+44) ----
#pragma unroll
        for (int rr = 0; rr < 12; rr++) {
            const int row = warp + rr * 4;
            float s = 0.f;
#pragma unroll
            for (int i = 0; i < 4; i++) {
                const int w = row * 128 + ((lane + 32 * i + row * 4) & 127);
                uint32_t u = Zs32[w];
                __nv_bfloat162 b = *reinterpret_cast<__nv_bfloat162*>(&u);
                s += __bfloat162float(b.x) + __bfloat162float(b.y);
            }
#pragma unroll
            for (int off = 16; off; off >>= 1)
                s += __shfl_xor_sync(0xffffffffu, s, off);
            if (lane == 0) us_acc[row] += s;
        }

        // ---- Gram mma: D[32x32] += Z[0:32] * Z[16:48]^T over 256 columns ----
#pragma unroll
        for (int kk = 0; kk < TILE / 16; kk++) {
            const int k0 = kk * 16 + t4 * 2;
            const int ra = m_off + g4;
            uint32_t a0 = lds_u32(&zh[ra * TILE + ((k0 + 8 * ra) & 255)]);
            uint32_t a1 = lds_u32(&zh[(ra + 8) * TILE + ((k0 + 8 * (ra + 8)) & 255)]);
            uint32_t a2 = lds_u32(&zh[ra * TILE + ((k0 + 8 + 8 * ra) & 255)]);
            uint32_t a3 = lds_u32(&zh[(ra + 8) * TILE + ((k0 + 8 + 8 * (ra + 8)) & 255)]);
#pragma unroll
            for (int j = 0; j < 2; j++) {
                const int rb = 16 + n_off + 8 * j + g4;
                uint32_t b0 = lds_u32(&zh[rb * TILE + ((k0 + 8 * rb) & 255)]);
                uint32_t b1 = lds_u32(&zh[rb * TILE + ((k0 + 8 + 8 * rb) & 255)]);
                mma_m16n8k16(d[j][0], d[j][1], d[j][2], d[j][3],
                             a0, a1, a2, a3, b0, b1);
            }
        }
        __syncthreads();
    }

    // ---- write deterministic per-CTA partials ----
    float* pp = g_part + (size_t)blockIdx.x * PART_STRIDE;
    const int row0 = m_off + g4;
#pragma unroll
    for (int j = 0; j < 2; j++) {
        const int colp = n_off + 8 * j + t4 * 2;
        pp[row0 * 32 + colp]           = d[j][0];
        pp[row0 * 32 + colp + 1]       = d[j][1];
        pp[(row0 + 8) * 32 + colp]     = d[j][2];
        pp[(row0 + 8) * 32 + colp + 1] = d[j][3];
    }
    if (lane == 0) {
#pragma unroll
        for (int rr = 0; rr < 12; rr++) {
            const int row = warp + rr * 4;
            pp[GRAM_E + row] = us_acc[row];
        }
    }
}

// ============================================================================
// Reduce partials (deterministic)
// ============================================================================
__global__ void k_reduce(int nb)
{
    const int e = blockIdx.x * blockDim.x + threadIdx.x;
    if (e >= PART_STRIDE) return;
    float s = 0.f;
    int c = 0;
#pragma unroll 4
    for (; c + 4 <= nb; c += 4) {
        s += g_part[(size_t)c * PART_STRIDE + e]
           + g_part[(size_t)(c + 1) * PART_STRIDE + e]
           + g_part[(size_t)(c + 2) * PART_STRIDE + e]
           + g_part[(size_t)(c + 3) * PART_STRIDE + e];
    }
    for (; c < nb; c++) s += g_part[(size_t)c * PART_STRIDE + e];
    if (e < GRAM_E) g_gram[e] = s;
    else            g_u[e - GRAM_E] = s;
}

// ============================================================================
// Pass 2 (1 block, 64 threads): logits -> softmax -> A[64x32], e[64], rs[64]
// ============================================================================
__global__ void k_pass2(const float* __restrict__ gamma,
                        const float* __restrict__ beta,
                        const float* __restrict__ cw,
                        const float* __restrict__ cb,
                        float Nf)
{
    __shared__ float Gs[GRAM_E];
    __shared__ float us[UE];
    __shared__ float gs[64], bs[64];

    const int c = threadIdx.x;
    for (int i = c; i < GRAM_E; i += 64) Gs[i] = g_gram[i];
    if (c < UE) us[c] = g_u[c];
    gs[c] = gamma[c];
    bs[c] = beta[c];
    __syncthreads();

    const float wq = cw[c], bq = cb[c];
    const int   iq = c / 3;
    const float gi = gs[iq], bi = bs[iq], ui = us[iq];
    const float ti = gi * ui + Nf * bi;

    float L[64];
    float mx = -1e30f;
#pragma unroll 1
    for (int b2 = 0; b2 < 64; b2++) {
        const int   ik = (64 + b2) / 3;
        const float wk = cw[64 + b2], bk = cb[64 + b2];
        const float gj = gs[ik], bj = bs[ik], uj = us[ik];
        const float tj = gj * uj + Nf * bj;
        const float Gz = Gs[iq * 32 + (ik - 16)];
        const float S  = gi * gj * Gz + gi * bj * ui + bi * gj * uj + Nf * bi * bj;
        const float l  = 0.125f * (wq * wk * S + wq * bk * ti + bq * wk * tj + Nf * bq * bk);
        L[b2] = l;
        mx = fmaxf(mx, l);
    }
    float se = 0.f;
#pragma unroll 1
    for (int b2 = 0; b2 < 64; b2++) {
        const float ev = expf(L[b2] - mx);
        L[b2] = ev;
        se += ev;
    }
    const float inv = 1.f / se;

    float eacc = 0.f;
#pragma unroll 1
    for (int b2 = 0; b2 < 64; b2++) {
        L[b2] *= inv;
        eacc += L[b2] * cb[128 + b2];
    }

    float rssum = 0.f;
#pragma unroll 1
    for (int j = 32; j < 64; j++) {
        float P = 0.f;
        const int b0 = 3 * j - 128;
#pragma unroll
        for (int d = 0; d < 3; d++) {
            const int bb = b0 + d;
            if (bb >= 0 && bb < 64) P += L[bb] * cw[128 + bb];
        }
        const float Av = P * gs[j];
        const __nv_bfloat16 ab = __float2bfloat16(Av);
        g_A[c * 32 + (j - 32)] = ab;
        rssum += __bfloat162float(ab);
        eacc  += P * bs[j];
    }
    g_e[c]  = eacc;
    g_rs[c] = rssum;
}

// ============================================================================
// Pass 3: out = x + r*(A@x - mu*rs) + e; 128 threads, TILE=256, 8 CTAs/SM
// ============================================================================
__global__ __launch_bounds__(NTHR, 8) void k_pass3(const float* __restrict__ x,
                                                   float* __restrict__ out, int N)
{
    __shared__ uint32_t XsT32[TILE * XPITCH_W];   // 17.4KB
    __shared__ float mus[TILE], rvs[TILE];
    __nv_bfloat16* xh = reinterpret_cast<__nv_bfloat16*>(XsT32);

    const int tid  = threadIdx.x;
    const int warp = tid >> 5;     // 0..3
    const int lane = tid & 31;
    const int g4   = lane >> 2;
    const int t4   = lane & 3;

    const long col0 = (long)blockIdx.x * TILE;
    const bool fast = (col0 + TILE <= (long)N) && ((N & 1) == 0);

    if (fast) {
        const int c0 = 2 * tid;
        const float* xp = x + col0 + c0;
        float s1x = 0.f, s1y = 0.f, s2x = 0.f, s2y = 0.f;
#pragma unroll
        for (int r = 0; r < 32; r++) {
            float2 v = __ldg(reinterpret_cast<const float2*>(xp + (size_t)r * N));
            s1x += v.x; s1y += v.y;
            s2x = fmaf(v.x, v.x, s2x);
            s2y = fmaf(v.y, v.y, s2y);
        }
#pragma unroll
        for (int rp = 0; rp < 16; rp++) {
            float2 va = __ldg(reinterpret_cast<const float2*>(xp + (size_t)(32 + 2 * rp) * N));
            float2 vb = __ldg(reinterpret_cast<const float2*>(xp + (size_t)(33 + 2 * rp) * N));
            s1x += va.x + vb.x; s1y += va.y + vb.y;
            s2x = fmaf(va.x, va.x, s2x); s2x = fmaf(vb.x, vb.x, s2x);
            s2y = fmaf(va.y, va.y, s2y); s2y = fmaf(vb.y, vb.y, s2y);
            XsT32[c0 * XPITCH_W + rp]       = pack_bf16(va.x, vb.x);
            XsT32[(c0 + 1) * XPITCH_W + rp] = pack_bf16(va.y, vb.y);
        }
        const float mux = s1x * (1.f / 64.f), muy = s1y * (1.f / 64.f);
        mus[c0]     = mux;
        mus[c0 + 1] = muy;
        rvs[c0]     = rsqrtf(s2x * (1.f / 64.f) - mux * mux + LN_EPS);
        rvs[c0 + 1] = rsqrtf(s2y * (1.f / 64.f) - muy * muy + LN_EPS);
    } else {
#pragma unroll 1
        for (int cc = 0; cc < 2; cc++) {
            const int lc = 2 * tid + cc;
            const long col = col0 + lc;
            float s1 = 0.f, s2 = 0.f;
            if (col < N) {
                const float* xp = x + col;
#pragma unroll 1
                for (int r = 0; r < 64; r++) {
                    float v = __ldg(xp + (size_t)r * N);
                    s1 += v; s2 = fmaf(v, v, s2);
                    if (r >= 32) xh[lc * (2 * XPITCH_W) + (r - 32)] = __float2bfloat16(v);
                }
            } else {
#pragma unroll 1
                for (int r = 0; r < 32; r++)
                    xh[lc * (2 * XPITCH_W) + r] = __float2bfloat16(0.f);
            }
            const float mu = s1 * (1.f / 64.f);
            mus[lc] = mu;
            rvs[lc] = rsqrtf(s2 * (1.f / 64.f) - mu * mu + LN_EPS);
        }
    }
    __syncthreads();

    // ---- phase B: warp w owns m-tile w (rows 16w..16w+15), all 256 cols ----
    const int m_off = warp << 4;
    const int row0  = m_off + g4;
    const int row1  = row0 + 8;

    uint32_t Af[2][4];
#pragma unroll
    for (int s = 0; s < 2; s++) {
        const int k0 = s * 16 + t4 * 2;
        Af[s][0] = *reinterpret_cast<const uint32_t*>(&g_A[row0 * 32 + k0]);
        Af[s][1] = *reinterpret_cast<const uint32_t*>(&g_A[row1 * 32 + k0]);
        Af[s][2] = *reinterpret_cast<const uint32_t*>(&g_A[row0 * 32 + k0 + 8]);
        Af[s][3] = *reinterpret_cast<const uint32_t*>(&g_A[row1 * 32 + k0 + 8]);
    }
    const float e0  = g_e[row0],  e1  = g_e[row1];
    const float rs0 = g_rs[row0], rs1 = g_rs[row1];

#pragma unroll 4
    for (int nc = 0; nc < TILE / 8; nc++) {
        const int nb   = nc * 8;
        const int nrow = nb + g4;
        const int lcol = nb + t4 * 2;
        const long gc  = col0 + lcol;

        float2 xv0, xv1;
        bool pair_ok = (gc + 1 < (long)N);
        if (pair_ok) {
            xv0 = __ldg(reinterpret_cast<const float2*>(x + (size_t)row0 * N + gc));
            xv1 = __ldg(reinterpret_cast<const float2*>(x + (size_t)row1 * N + gc));
        }

        const uint32_t* bp = &XsT32[nrow * XPITCH_W];
        uint32_t b00 = bp[t4];
        uint32_t b01 = bp[t4 + 4];
        uint32_t b10 = bp[t4 + 8];
        uint32_t b11 = bp[t4 + 12];

        float c0 = 0.f, c1 = 0.f, c2 = 0.f, c3 = 0.f;
        mma_m16n8k16(c0, c1, c2, c3, Af[0][0], Af[0][1], Af[0][2], Af[0][3], b00, b01);
        mma_m16n8k16(c0, c1, c2, c3, Af[1][0], Af[1][1], Af[1][2], Af[1][3], b10, b11);

        if (pair_ok) {
            const float mu0 = mus[lcol],     mu1 = mus[lcol + 1];
            const float rv0 = rvs[lcol],     rv1 = rvs[lcol + 1];
            float2 o0, o1;
            o0.x = xv0.x + e0 + rv0 * (c0 - mu0 * rs0);
            o0.y = xv0.y + e0 + rv1 * (c1 - mu1 * rs0);
            o1.x = xv1.x + e1 + rv0 * (c2 - mu0 * rs1);
            o1.y = xv1.y + e1 + rv1 * (c3 - mu1 * rs1);
            __stcs(reinterpret_cast<float2*>(out + (size_t)row0 * N + gc), o0);
            __stcs(reinterpret_cast<float2*>(out + (size_t)row1 * N + gc), o1);
        } else if (gc < (long)N) {
            const float mu0 = mus[lcol], rv0 = rvs[lcol];
            const float xa = x[(size_t)row0 * N + gc];
            out[(size_t)row0 * N + gc] = xa + e0 + rv0 * (c0 - mu0 * rs0);
            const float xb = x[(size_t)row1 * N + gc];
            out[(size_t)row1 * N + gc] = xb + e1 + rv0 * (c2 - mu0 * rs1);
        }
    }
}

// ============================================================================
extern "C" void kernel_launch(void* const* d_in, const int* in_sizes, int n_in,
                              void* d_out, int out_size)
{
    const float* x     = (const float*)d_in[0];
    const float* gamma = (const float*)d_in[1];
    const float* beta  = (const float*)d_in[2];
    const float* cw    = (const float*)d_in[3];
    const float* cb    = (const float*)d_in[4];
    float* out = (float*)d_out;

    const int N = in_sizes[0] / 64;
    const int nchunks = (N + TILE - 1) / TILE;
    const int nb1 = nchunks < P1_NCTA ? nchunks : P1_NCTA;

    k_pass1<<<nb1, NTHR>>>(x, N, nchunks);
    k_reduce<<<(PART_STRIDE + 255) / 256, 256>>>(nb1);
    k_pass2<<<1, 64>>>(gamma, beta, cw, cb, (float)N);
    k_pass3<<<nchunks, NTHR>>>(x, out, N);
}